// round 1
// baseline (speedup 1.0000x reference)
#include <cuda_runtime.h>

#define BB 256
#define TT 4096
#define NH 8

// Scratch: intermediate hidden sequences + layer-1 output (alloc-free scratch).
__device__ __align__(16) float g_h1f[BB*TT*NH];
__device__ __align__(16) float g_h1b[BB*TT*NH];
__device__ __align__(16) float g_y1 [BB*TT*NH];
__device__ __align__(16) float g_h2f[BB*TT*NH];
__device__ __align__(16) float g_h2b[BB*TT*NH];

__device__ __forceinline__ float ex2f(float x){ float y; asm("ex2.approx.f32 %0, %1;":"=f"(y):"f"(x)); return y; }
__device__ __forceinline__ float rcpf(float x){ float y; asm("rcp.approx.f32 %0, %1;":"=f"(y):"f"(x)); return y; }

// One LSTM scan per 8 lanes; 4 scans per warp; scan = (batch, direction).
// Lane j owns hidden index j and computes gate rows {j, 8+j, 16+j, 24+j}.
// Weights are pre-scaled at load:  i,f,o rows by -log2(e)  (sigmoid via ex2),
// g rows by -2*log2(e) (tanh via ex2), so no scaling FMUL sits on the
// recurrence critical path.
__global__ __launch_bounds__(32,1)
void lstm_scan_kernel(const float* __restrict__ x_in,
                      const float* __restrict__ Wih_f, const float* __restrict__ Whh_f, const float* __restrict__ b_f,
                      const float* __restrict__ Wih_b, const float* __restrict__ Whh_b, const float* __restrict__ b_b,
                      int layer)
{
    const float* x = (layer == 0) ? x_in : g_y1;

    const int lane = threadIdx.x;      // 0..31
    const int sub  = lane >> 3;        // scan within warp: 0..3
    const int j    = lane & 7;         // hidden index
    const int scan = blockIdx.x * 4 + sub;   // 0..511
    const int b    = scan >> 1;
    const int rev  = scan & 1;

    const float* Wih = rev ? Wih_b : Wih_f;
    const float* Whh = rev ? Whh_b : Whh_f;
    const float* bia = rev ? b_b   : b_f;
    float* hout = (layer == 0) ? (rev ? g_h1b : g_h1f)
                               : (rev ? g_h2b : g_h2f);

    const float L2E = 1.4426950408889634f;
    const float scs[4] = { -L2E, -L2E, -2.f*L2E, -L2E };   // i, f, g, o

    float wih[4][8], whh[4][8], bs[4];
    #pragma unroll
    for (int g = 0; g < 4; ++g) {
        const int row = g * 8 + j;
        #pragma unroll
        for (int k = 0; k < 8; ++k) {
            wih[g][k] = Wih[row * 8 + k] * scs[g];
            whh[g][k] = Whh[row * 8 + k] * scs[g];
        }
        bs[g] = bia[row] * scs[g];
    }

    const float* xb = x    + (size_t)b * TT * NH;
    float*       ob = hout + (size_t)b * TT * NH;

    float c = 0.f, h = 0.f;
    const int base = lane & 24;        // first lane of this scan's 8-lane group

    // Software-pipelined x loads, distance 2 steps (~2 iterations > L2 latency).
    float4 buf[2][2];
    #pragma unroll
    for (int s = 0; s < 2; ++s) {
        const int t = rev ? (TT - 1 - s) : s;
        const float4* p = reinterpret_cast<const float4*>(xb + t * NH);
        buf[s][0] = p[0]; buf[s][1] = p[1];
    }

    for (int n = 0; n < TT; n += 2) {
        float4 cur[2][2];
        cur[0][0] = buf[0][0]; cur[0][1] = buf[0][1];
        cur[1][0] = buf[1][0]; cur[1][1] = buf[1][1];

        // Prefetch steps n+2, n+3 (clamped; extra loads harmless & unused).
        #pragma unroll
        for (int s = 0; s < 2; ++s) {
            int np = n + 2 + s; if (np > TT - 1) np = TT - 1;
            const int t = rev ? (TT - 1 - np) : np;
            const float4* p = reinterpret_cast<const float4*>(xb + t * NH);
            buf[s][0] = p[0]; buf[s][1] = p[1];
        }

        #pragma unroll
        for (int s = 0; s < 2; ++s) {
            const int t = rev ? (TT - 1 - (n + s)) : (n + s);
            const float xv[8] = { cur[s][0].x, cur[s][0].y, cur[s][0].z, cur[s][0].w,
                                  cur[s][1].x, cur[s][1].y, cur[s][1].z, cur[s][1].w };

            // Input projection + bias (h-independent: hides under shuffle/MUFU stalls).
            float z[4];
            #pragma unroll
            for (int g = 0; g < 4; ++g) {
                float a = bs[g];
                #pragma unroll
                for (int k = 0; k < 8; ++k) a = fmaf(wih[g][k], xv[k], a);
                z[g] = a;
            }

            // Broadcast h across the 8-lane group (critical path starts here).
            float hv[8];
            #pragma unroll
            for (int k = 0; k < 8; ++k)
                hv[k] = __shfl_sync(0xffffffffu, h, base + k);

            // Recurrence, two accumulators per gate to halve the FMA chain.
            #pragma unroll
            for (int g = 0; g < 4; ++g) {
                float a = z[g], a2 = 0.f;
                #pragma unroll
                for (int k = 0; k < 4; ++k) {
                    a  = fmaf(whh[g][k],     hv[k],     a);
                    a2 = fmaf(whh[g][4 + k], hv[4 + k], a2);
                }
                z[g] = a + a2;
            }

            // Gates: z already = -log2e*zi etc., so sigma = rcp(1 + ex2(z)).
            const float si = rcpf(1.f + ex2f(z[0]));
            const float sf = rcpf(1.f + ex2f(z[1]));
            const float tg = fmaf(2.f, rcpf(1.f + ex2f(z[2])), -1.f);
            const float so = rcpf(1.f + ex2f(z[3]));

            c = fmaf(sf, c, si * tg);
            const float tc = fmaf(2.f, rcpf(1.f + ex2f(c * (-2.f * L2E))), -1.f);
            h = so * tc;

            ob[t * NH + j] = h;
        }
    }
}

// y[b,t,o] = bl[o] + sum_k W[o,k]*hf[b,t,k] + sum_k W[o,8+k]*hb[b,t,k]
// layer==0: (h1f,h1b) -> g_y1 ; layer==1: (h2f,h2b) -> out_final
__global__ void linear_kernel(int layer, const float* __restrict__ W,
                              const float* __restrict__ bl, float* __restrict__ out_final)
{
    __shared__ float sW[128];
    __shared__ float sb[8];
    const int tid = threadIdx.x;
    if (tid < 128) sW[tid] = W[tid];
    if (tid < 8)   sb[tid] = bl[tid];
    __syncthreads();

    const size_t i = (size_t)blockIdx.x * blockDim.x + tid;   // (b,t) index
    const float* hf = (layer == 0 ? g_h1f : g_h2f) + i * NH;
    const float* hb = (layer == 0 ? g_h1b : g_h2b) + i * NH;
    float*       y  = (layer == 0 ? g_y1  : out_final) + i * NH;

    const float4 f0 = reinterpret_cast<const float4*>(hf)[0];
    const float4 f1 = reinterpret_cast<const float4*>(hf)[1];
    const float4 g0 = reinterpret_cast<const float4*>(hb)[0];
    const float4 g1 = reinterpret_cast<const float4*>(hb)[1];
    const float in[16] = { f0.x, f0.y, f0.z, f0.w, f1.x, f1.y, f1.z, f1.w,
                           g0.x, g0.y, g0.z, g0.w, g1.x, g1.y, g1.z, g1.w };

    float r[8];
    #pragma unroll
    for (int o = 0; o < 8; ++o) {
        float a = sb[o];
        #pragma unroll
        for (int k = 0; k < 16; ++k) a = fmaf(sW[o * 16 + k], in[k], a);
        r[o] = a;
    }
    float4 o0 = make_float4(r[0], r[1], r[2], r[3]);
    float4 o1 = make_float4(r[4], r[5], r[6], r[7]);
    reinterpret_cast<float4*>(y)[0] = o0;
    reinterpret_cast<float4*>(y)[1] = o1;
}

extern "C" void kernel_launch(void* const* d_in, const int* in_sizes, int n_in,
                              void* d_out, int out_size)
{
    const float* x     = (const float*)d_in[0];
    const float* Wih1f = (const float*)d_in[1];
    const float* Whh1f = (const float*)d_in[2];
    const float* b1f   = (const float*)d_in[3];
    const float* Wih1b = (const float*)d_in[4];
    const float* Whh1b = (const float*)d_in[5];
    const float* b1b   = (const float*)d_in[6];
    const float* Wih2f = (const float*)d_in[7];
    const float* Whh2f = (const float*)d_in[8];
    const float* b2f   = (const float*)d_in[9];
    const float* Wih2b = (const float*)d_in[10];
    const float* Whh2b = (const float*)d_in[11];
    const float* b2b   = (const float*)d_in[12];
    const float* W1    = (const float*)d_in[13];
    const float* bl1   = (const float*)d_in[14];
    const float* W2    = (const float*)d_in[15];
    const float* bl2   = (const float*)d_in[16];
    float* out = (float*)d_out;

    const int nscans_blocks = (BB * 2) / 4;       // 128 blocks x 1 warp
    const int lin_blocks    = (BB * TT) / 256;    // 4096 blocks

    lstm_scan_kernel<<<nscans_blocks, 32>>>(x, Wih1f, Whh1f, b1f, Wih1b, Whh1b, b1b, 0);
    linear_kernel<<<lin_blocks, 256>>>(0, W1, bl1, nullptr);
    lstm_scan_kernel<<<nscans_blocks, 32>>>(nullptr, Wih2f, Whh2f, b2f, Wih2b, Whh2b, b2b, 1);
    linear_kernel<<<lin_blocks, 256>>>(1, W2, bl2, out);
}

// round 2
// speedup vs baseline: 1.4557x; 1.4557x over previous
#include <cuda_runtime.h>

#define BB 256
#define TT 4096
#define NH 8

// Scratch (alloc-free): intermediate hidden sequences + layer-1 output.
__device__ __align__(16) float g_h1f[BB*TT*NH];
__device__ __align__(16) float g_h1b[BB*TT*NH];
__device__ __align__(16) float g_y1 [BB*TT*NH];
__device__ __align__(16) float g_h2f[BB*TT*NH];
__device__ __align__(16) float g_h2b[BB*TT*NH];

typedef unsigned long long ull;

__device__ __forceinline__ ull pk2(float lo, float hi){ ull r; asm("mov.b64 %0,{%1,%2};":"=l"(r):"f"(lo),"f"(hi)); return r; }
__device__ __forceinline__ void upk2(ull v, float& lo, float& hi){ asm("mov.b64 {%0,%1},%2;":"=f"(lo),"=f"(hi):"l"(v)); }
__device__ __forceinline__ ull fma2(ull a, ull b, ull c){ ull d; asm("fma.rn.f32x2 %0,%1,%2,%3;":"=l"(d):"l"(a),"l"(b),"l"(c)); return d; }
__device__ __forceinline__ ull mul2(ull a, ull b){ ull d; asm("mul.rn.f32x2 %0,%1,%2;":"=l"(d):"l"(a),"l"(b)); return d; }
__device__ __forceinline__ ull add2(ull a, ull b){ ull d; asm("add.rn.f32x2 %0,%1,%2;":"=l"(d):"l"(a),"l"(b)); return d; }
__device__ __forceinline__ float tanhx(float x){ float y; asm("tanh.approx.f32 %0,%1;":"=f"(y):"f"(x)); return y; }

// One LSTM scan per 8 lanes; 4 scans per warp (SIMD); scan = (batch, direction).
// Lane j owns hidden index j and computes gate rows {j, 8+j, 16+j, 24+j}.
// Nonlinearities via MUFU.TANH: sigma(x) = 0.5 + 0.5*tanh(x/2); the 0.5 arg
// scale is pre-folded into the i/f/o weight rows so no scaling op sits on the
// recurrence path. All dot products run as packed fma.rn.f32x2.
__global__ __launch_bounds__(32,1)
void lstm_scan_kernel(const float* __restrict__ x_in,
                      const float* __restrict__ Wih_f, const float* __restrict__ Whh_f, const float* __restrict__ b_f,
                      const float* __restrict__ Wih_b, const float* __restrict__ Whh_b, const float* __restrict__ b_b,
                      int layer)
{
    const float* x = (layer == 0) ? x_in : g_y1;

    const int lane = threadIdx.x;            // 0..31
    const int sub  = lane >> 3;               // scan within warp 0..3
    const int j    = lane & 7;                // hidden index
    const int scan = blockIdx.x * 4 + sub;    // 0..511
    const int b    = scan >> 1;
    const int rev  = scan & 1;
    const int base = lane & 24;               // first lane of this 8-lane group

    const float* Wih = rev ? Wih_b : Wih_f;
    const float* Whh = rev ? Whh_b : Whh_f;
    const float* bia = rev ? b_b   : b_f;
    float* hout = (layer == 0) ? (rev ? g_h1b : g_h1f)
                               : (rev ? g_h2b : g_h2f);

    // Pre-scaled, pre-packed weights: gates i,f,o scaled 0.5 (tanh-sigmoid),
    // gate g unscaled.
    ull wih2[4][4], whh2[4][4], bz[4];
    #pragma unroll
    for (int g = 0; g < 4; ++g) {
        const float sc = (g == 2) ? 1.0f : 0.5f;
        const int row = g * 8 + j;
        #pragma unroll
        for (int m = 0; m < 4; ++m) {
            wih2[g][m] = pk2(Wih[row*8 + 2*m] * sc, Wih[row*8 + 2*m + 1] * sc);
            whh2[g][m] = pk2(Whh[row*8 + 2*m] * sc, Whh[row*8 + 2*m + 1] * sc);
        }
        bz[g] = pk2(bia[row] * sc, 0.0f);
    }

    const float* xb = x + (size_t)b * TT * NH;
    float* ob = hout + (size_t)b * TT * NH + j + (rev ? (size_t)(TT-1) * NH : 0);
    const int ostep = rev ? -NH : NH;

    float c = 0.f, h = 0.f;

    // Prefetched x (8 floats = 4 packed pairs per step), distance 2 steps.
    ull xq[2][4];
    #pragma unroll
    for (int s = 0; s < 2; ++s) {
        const int t = rev ? (TT - 1 - s) : s;
        const ulonglong2* p = reinterpret_cast<const ulonglong2*>(xb + (size_t)t * NH);
        ulonglong2 a = p[0], d = p[1];
        xq[s][0] = a.x; xq[s][1] = a.y; xq[s][2] = d.x; xq[s][3] = d.y;
    }

    for (int n = 0; n < TT; n += 2) {
        ull cur[2][4];
        #pragma unroll
        for (int s = 0; s < 2; ++s) {
            cur[s][0]=xq[s][0]; cur[s][1]=xq[s][1]; cur[s][2]=xq[s][2]; cur[s][3]=xq[s][3];
        }
        // Prefetch steps n+2, n+3 (index clamped; duplicate loads harmless).
        #pragma unroll
        for (int s = 0; s < 2; ++s) {
            int np = n + 2 + s; np = np > TT-1 ? TT-1 : np;
            const int t = rev ? (TT - 1 - np) : np;
            const ulonglong2* p = reinterpret_cast<const ulonglong2*>(xb + (size_t)t * NH);
            ulonglong2 a = p[0], d = p[1];
            xq[s][0] = a.x; xq[s][1] = a.y; xq[s][2] = d.x; xq[s][3] = d.y;
        }

        #pragma unroll
        for (int s = 0; s < 2; ++s) {
            // Broadcast h across the 8-lane group; form packed pairs.
            float hv[8];
            #pragma unroll
            for (int k = 0; k < 8; ++k)
                hv[k] = __shfl_sync(0xffffffffu, h, base + k);
            ull hp[4];
            #pragma unroll
            for (int m = 0; m < 4; ++m) hp[m] = pk2(hv[2*m], hv[2*m+1]);

            // Gate pre-activations: packed input projection + packed recurrence.
            float z[4];
            #pragma unroll
            for (int g = 0; g < 4; ++g) {
                ull aA = fma2(wih2[g][0], cur[s][0], bz[g]);
                ull aB = mul2(wih2[g][1], cur[s][1]);
                aA = fma2(wih2[g][2], cur[s][2], aA);
                aB = fma2(wih2[g][3], cur[s][3], aB);
                aA = fma2(whh2[g][0], hp[0], aA);
                aB = fma2(whh2[g][1], hp[1], aB);
                aA = fma2(whh2[g][2], hp[2], aA);
                aB = fma2(whh2[g][3], hp[3], aB);
                ull sm = add2(aA, aB);
                float lo, hi; upk2(sm, lo, hi);
                z[g] = lo + hi;
            }

            const float ti = tanhx(z[0]);
            const float tf = tanhx(z[1]);
            const float tg = tanhx(z[2]);
            const float to = tanhx(z[3]);
            const float si = fmaf(0.5f, ti, 0.5f);
            const float sf = fmaf(0.5f, tf, 0.5f);
            const float so = fmaf(0.5f, to, 0.5f);

            c = fmaf(sf, c, si * tg);
            const float tc = tanhx(c);
            h = so * tc;

            *ob = h; ob += ostep;
        }
    }
}

// y[b,t,o] = bl[o] + W[o,0:8]*hf + W[o,8:16]*hb
__global__ void linear_kernel(int layer, const float* __restrict__ W,
                              const float* __restrict__ bl, float* __restrict__ out_final)
{
    __shared__ float sW[128];
    __shared__ float sb[8];
    const int tid = threadIdx.x;
    if (tid < 128) sW[tid] = W[tid];
    if (tid < 8)   sb[tid] = bl[tid];
    __syncthreads();

    const size_t i = (size_t)blockIdx.x * blockDim.x + tid;
    const float* hf = (layer == 0 ? g_h1f : g_h2f) + i * NH;
    const float* hb = (layer == 0 ? g_h1b : g_h2b) + i * NH;
    float*       y  = (layer == 0 ? g_y1  : out_final) + i * NH;

    const float4 f0 = reinterpret_cast<const float4*>(hf)[0];
    const float4 f1 = reinterpret_cast<const float4*>(hf)[1];
    const float4 g0 = reinterpret_cast<const float4*>(hb)[0];
    const float4 g1 = reinterpret_cast<const float4*>(hb)[1];
    const float in[16] = { f0.x, f0.y, f0.z, f0.w, f1.x, f1.y, f1.z, f1.w,
                           g0.x, g0.y, g0.z, g0.w, g1.x, g1.y, g1.z, g1.w };

    float r[8];
    #pragma unroll
    for (int o = 0; o < 8; ++o) {
        float a = sb[o];
        #pragma unroll
        for (int k = 0; k < 16; ++k) a = fmaf(sW[o * 16 + k], in[k], a);
        r[o] = a;
    }
    reinterpret_cast<float4*>(y)[0] = make_float4(r[0], r[1], r[2], r[3]);
    reinterpret_cast<float4*>(y)[1] = make_float4(r[4], r[5], r[6], r[7]);
}

extern "C" void kernel_launch(void* const* d_in, const int* in_sizes, int n_in,
                              void* d_out, int out_size)
{
    const float* x     = (const float*)d_in[0];
    const float* Wih1f = (const float*)d_in[1];
    const float* Whh1f = (const float*)d_in[2];
    const float* b1f   = (const float*)d_in[3];
    const float* Wih1b = (const float*)d_in[4];
    const float* Whh1b = (const float*)d_in[5];
    const float* b1b   = (const float*)d_in[6];
    const float* Wih2f = (const float*)d_in[7];
    const float* Whh2f = (const float*)d_in[8];
    const float* b2f   = (const float*)d_in[9];
    const float* Wih2b = (const float*)d_in[10];
    const float* Whh2b = (const float*)d_in[11];
    const float* b2b   = (const float*)d_in[12];
    const float* W1    = (const float*)d_in[13];
    const float* bl1   = (const float*)d_in[14];
    const float* W2    = (const float*)d_in[15];
    const float* bl2   = (const float*)d_in[16];
    float* out = (float*)d_out;

    const int scan_blocks = (BB * 2) / 4;      // 128 blocks x 1 warp
    const int lin_blocks  = (BB * TT) / 256;   // 4096 blocks

    lstm_scan_kernel<<<scan_blocks, 32>>>(x, Wih1f, Whh1f, b1f, Wih1b, Whh1b, b1b, 0);
    linear_kernel<<<lin_blocks, 256>>>(0, W1, bl1, nullptr);
    lstm_scan_kernel<<<scan_blocks, 32>>>(nullptr, Wih2f, Whh2f, b2f, Wih2b, Whh2b, b2b, 1);
    linear_kernel<<<lin_blocks, 256>>>(1, W2, bl2, out);
}

// round 4
// speedup vs baseline: 1.7540x; 1.2049x over previous
#include <cuda_runtime.h>

#define BB 256
#define TT 4096
#define NH 8

// Scratch (alloc-free): intermediate hidden sequences + layer-1 output.
__device__ __align__(16) float g_h1f[BB*TT*NH];
__device__ __align__(16) float g_h1b[BB*TT*NH];
__device__ __align__(16) float g_y1 [BB*TT*NH];
__device__ __align__(16) float g_h2f[BB*TT*NH];
__device__ __align__(16) float g_h2b[BB*TT*NH];

typedef unsigned long long ull;

__device__ __forceinline__ ull pk2(float lo, float hi){ ull r; asm("mov.b64 %0,{%1,%2};":"=l"(r):"f"(lo),"f"(hi)); return r; }
__device__ __forceinline__ void upk2(ull v, float& lo, float& hi){ asm("mov.b64 {%0,%1},%2;":"=f"(lo),"=f"(hi):"l"(v)); }
__device__ __forceinline__ ull fma2(ull a, ull b, ull c){ ull d; asm("fma.rn.f32x2 %0,%1,%2,%3;":"=l"(d):"l"(a),"l"(b),"l"(c)); return d; }
__device__ __forceinline__ ull mul2(ull a, ull b){ ull d; asm("mul.rn.f32x2 %0,%1,%2;":"=l"(d):"l"(a),"l"(b)); return d; }
__device__ __forceinline__ ull add2(ull a, ull b){ ull d; asm("add.rn.f32x2 %0,%1,%2;":"=l"(d):"l"(a),"l"(b)); return d; }
__device__ __forceinline__ float tanhx(float x){ float y; asm("tanh.approx.f32 %0,%1;":"=f"(y):"f"(x)); return y; }

// ============================================================================
// One LSTM scan per WARP. Lane = gate*8 + j owns ONE gate row (of 32 = 4H).
// Per step, each lane computes z_row = b + Wih_row·x + Whh_row·h (packed f32x2),
// t = tanh(z). Then a 4-shuffle gather brings (ti,tf,tg,to) for index j=lane&7
// to every lane; all lanes redundantly update c_j, h_j (so h is replicated and
// the next-step h broadcast is shfl(h, k), k=0..7).
// Sigmoid via tanh: sigma(z)=0.5+0.5*tanh(z/2); the /2 is pre-folded into the
// i,f,o weight rows. Only lanes 0..7 store h.
// 512 warps (= 512 scans) on 128 blocks x 128 threads -> 1 warp per SMSP,
// full-chip. rev is warp-uniform.
// ============================================================================
struct ScanCtx {
    ull wih2[4], whh2[4], bz;
    const float* xp;   // walking x pointer (lane-uniform)
    long xstep;        // +NH or -NH
    int  j;
};

__device__ __forceinline__ void load_x4(const ScanCtx& S, long n, ull q[4]) {
    const ulonglong2* p = reinterpret_cast<const ulonglong2*>(S.xp + n * S.xstep);
    ulonglong2 a = p[0], b = p[1];
    q[0] = a.x; q[1] = a.y; q[2] = b.x; q[3] = b.y;
}

__device__ __forceinline__ void step(const ScanCtx& S, const ull xq[4],
                                     float& c, float& h, int lane, float* obj) {
    // x projection + bias (h-independent; fills latency shadows).
    ull aA = fma2(S.wih2[0], xq[0], S.bz);
    ull aB = mul2(S.wih2[1], xq[1]);
    aA = fma2(S.wih2[2], xq[2], aA);
    aB = fma2(S.wih2[3], xq[3], aB);

    // Broadcast h_0..h_7 (lane k<8 holds h_k; replicated in upper groups).
    float hv0 = __shfl_sync(0xffffffffu, h, 0);
    float hv1 = __shfl_sync(0xffffffffu, h, 1);
    float hv2 = __shfl_sync(0xffffffffu, h, 2);
    float hv3 = __shfl_sync(0xffffffffu, h, 3);
    float hv4 = __shfl_sync(0xffffffffu, h, 4);
    float hv5 = __shfl_sync(0xffffffffu, h, 5);
    float hv6 = __shfl_sync(0xffffffffu, h, 6);
    float hv7 = __shfl_sync(0xffffffffu, h, 7);
    ull hp0 = pk2(hv0, hv1), hp1 = pk2(hv2, hv3);
    ull hp2 = pk2(hv4, hv5), hp3 = pk2(hv6, hv7);

    aA = fma2(S.whh2[0], hp0, aA);
    aB = fma2(S.whh2[1], hp1, aB);
    aA = fma2(S.whh2[2], hp2, aA);
    aB = fma2(S.whh2[3], hp3, aB);
    ull sm = add2(aA, aB);
    float lo, hi; upk2(sm, lo, hi);
    const float z = lo + hi;

    const float tz = tanhx(z);

    // Gather the 4 gate values for hidden index j to every lane.
    const float vi = __shfl_sync(0xffffffffu, tz, S.j);
    const float vf = __shfl_sync(0xffffffffu, tz, S.j + 8);
    const float vg = __shfl_sync(0xffffffffu, tz, S.j + 16);
    const float vo = __shfl_sync(0xffffffffu, tz, S.j + 24);

    const float si = fmaf(0.5f, vi, 0.5f);
    const float sf = fmaf(0.5f, vf, 0.5f);
    const float so = fmaf(0.5f, vo, 0.5f);
    c = fmaf(sf, c, si * vg);
    const float tc = tanhx(c);
    h = so * tc;

    if (lane < 8) *obj = h;
}

__global__ __launch_bounds__(128,1)
void lstm_scan_kernel(const float* __restrict__ x_in,
                      const float* __restrict__ Wih_f, const float* __restrict__ Whh_f, const float* __restrict__ b_f,
                      const float* __restrict__ Wih_b, const float* __restrict__ Whh_b, const float* __restrict__ b_b,
                      int layer)
{
    const float* x = (layer == 0) ? x_in : g_y1;

    const int lane = threadIdx.x & 31;
    const int g    = lane >> 3;           // gate 0..3 (i,f,g,o)
    const int j    = lane & 7;            // hidden index
    const int scan = blockIdx.x * 4 + (threadIdx.x >> 5);  // 0..511
    const int b    = scan >> 1;
    const int rev  = scan & 1;            // warp-uniform

    const float* Wih = rev ? Wih_b : Wih_f;
    const float* Whh = rev ? Whh_b : Whh_f;
    const float* bia = rev ? b_b   : b_f;
    float* hout = (layer == 0) ? (rev ? g_h1b : g_h1f)
                               : (rev ? g_h2b : g_h2f);

    ScanCtx S;
    S.j = j;
    const int row = g * 8 + j;
    const float sc = (g == 2) ? 1.0f : 0.5f;   // tanh-sigmoid arg prescale
    #pragma unroll
    for (int m = 0; m < 4; ++m) {
        S.wih2[m] = pk2(Wih[row*8 + 2*m] * sc, Wih[row*8 + 2*m + 1] * sc);
        S.whh2[m] = pk2(Whh[row*8 + 2*m] * sc, Whh[row*8 + 2*m + 1] * sc);
    }
    S.bz = pk2(bia[row] * sc, 0.0f);

    const float* xb = x + (size_t)b * TT * NH;
    S.xp    = rev ? xb + (size_t)(TT-1) * NH : xb;
    S.xstep = rev ? -NH : NH;
    float* ob = hout + (size_t)b * TT * NH + j + (rev ? (size_t)(TT-1) * NH : 0);
    const long ostep = rev ? -NH : NH;

    float c = 0.f, h = 0.f;

    // Double-buffered 4-step blocks: prefetch distance 4..8 steps (~600+ cyc,
    // covers DRAM on cold layer-1 reads).
    ull bufA[4][4], bufB[4][4];
    #pragma unroll
    for (int s = 0; s < 4; ++s) load_x4(S, s, bufA[s]);

    for (long n = 0; n < TT; n += 8) {
        // Prefetch steps n+4..n+7 into B, then consume A (steps n..n+3).
        #pragma unroll
        for (int s = 0; s < 4; ++s) {
            long t = n + 4 + s; t = t > TT-1 ? TT-1 : t;
            load_x4(S, t, bufB[s]);
        }
        #pragma unroll
        for (int s = 0; s < 4; ++s) {
            step(S, bufA[s], c, h, lane, ob); ob += ostep;
        }
        // Prefetch steps n+8..n+11 into A, then consume B (steps n+4..n+7).
        #pragma unroll
        for (int s = 0; s < 4; ++s) {
            long t = n + 8 + s; t = t > TT-1 ? TT-1 : t;
            load_x4(S, t, bufA[s]);
        }
        #pragma unroll
        for (int s = 0; s < 4; ++s) {
            step(S, bufB[s], c, h, lane, ob); ob += ostep;
        }
    }
}

// y[b,t,o] = bl[o] + W[o,0:8]*hf + W[o,8:16]*hb   (BW-bound, ~20us, leave as-is)
__global__ void linear_kernel(int layer, const float* __restrict__ W,
                              const float* __restrict__ bl, float* __restrict__ out_final)
{
    __shared__ float sW[128];
    __shared__ float sb[8];
    const int tid = threadIdx.x;
    if (tid < 128) sW[tid] = W[tid];
    if (tid < 8)   sb[tid] = bl[tid];
    __syncthreads();

    const size_t i = (size_t)blockIdx.x * blockDim.x + tid;
    const float* hf = (layer == 0 ? g_h1f : g_h2f) + i * NH;
    const float* hb = (layer == 0 ? g_h1b : g_h2b) + i * NH;
    float*       y  = (layer == 0 ? g_y1  : out_final) + i * NH;

    const float4 f0 = reinterpret_cast<const float4*>(hf)[0];
    const float4 f1 = reinterpret_cast<const float4*>(hf)[1];
    const float4 g0 = reinterpret_cast<const float4*>(hb)[0];
    const float4 g1 = reinterpret_cast<const float4*>(hb)[1];
    const float in[16] = { f0.x, f0.y, f0.z, f0.w, f1.x, f1.y, f1.z, f1.w,
                           g0.x, g0.y, g0.z, g0.w, g1.x, g1.y, g1.z, g1.w };

    float r[8];
    #pragma unroll
    for (int o = 0; o < 8; ++o) {
        float a = sb[o];
        #pragma unroll
        for (int k = 0; k < 16; ++k) a = fmaf(sW[o * 16 + k], in[k], a);
        r[o] = a;
    }
    reinterpret_cast<float4*>(y)[0] = make_float4(r[0], r[1], r[2], r[3]);
    reinterpret_cast<float4*>(y)[1] = make_float4(r[4], r[5], r[6], r[7]);
}

extern "C" void kernel_launch(void* const* d_in, const int* in_sizes, int n_in,
                              void* d_out, int out_size)
{
    const float* x     = (const float*)d_in[0];
    const float* Wih1f = (const float*)d_in[1];
    const float* Whh1f = (const float*)d_in[2];
    const float* b1f   = (const float*)d_in[3];
    const float* Wih1b = (const float*)d_in[4];
    const float* Whh1b = (const float*)d_in[5];
    const float* b1b   = (const float*)d_in[6];
    const float* Wih2f = (const float*)d_in[7];
    const float* Whh2f = (const float*)d_in[8];
    const float* b2f   = (const float*)d_in[9];
    const float* Wih2b = (const float*)d_in[10];
    const float* Whh2b = (const float*)d_in[11];
    const float* b2b   = (const float*)d_in[12];
    const float* W1    = (const float*)d_in[13];
    const float* bl1   = (const float*)d_in[14];
    const float* W2    = (const float*)d_in[15];
    const float* bl2   = (const float*)d_in[16];
    float* out = (float*)d_out;

    const int scan_blocks = (BB * 2) / 4;      // 128 blocks x 4 warps = 512 scans
    const int lin_blocks  = (BB * TT) / 256;

    lstm_scan_kernel<<<scan_blocks, 128>>>(x, Wih1f, Whh1f, b1f, Wih1b, Whh1b, b1b, 0);
    linear_kernel<<<lin_blocks, 256>>>(0, W1, bl1, nullptr);
    lstm_scan_kernel<<<scan_blocks, 128>>>(nullptr, Wih2f, Whh2f, b2f, Wih2b, Whh2b, b2b, 1);
    linear_kernel<<<lin_blocks, 256>>>(1, W2, bl2, out);
}